// round 14
// baseline (speedup 1.0000x reference)
#include <cuda_runtime.h>
#include <cstdint>
#include <math.h>

// ---------------------------------------------------------------------------
//   x: [4,16,64,64,64] f32    weights1/2: [2,4] f32    out: [4,32,32,32,32] f32
// <Z0> = v^T S v  ->  81 coeffs in double-angle basis (1, cos2a, sin2a),
// 2a = min(pi, pi*y). ONE kernel, 514 blocks = ONE wave at 4 blocks/SM:
//   blocks 0-1:   build W (warp-shuffle sim) -> g_W, raise flag
//   blocks 2-513: eval (2 l-points/thread) + zero their share of j>=16 half
// ---------------------------------------------------------------------------

#define MAXOPS 64
#define NBLOCKS 514

struct Plan {
    int n;
    int type[MAXOPS];   // 0=RX, 1=RY, 2=RZ, 3=CNOT
    int a[MAXOPS];      // rot wire, or cnot control
    int b[MAXOPS];      // cnot target
    int widx[MAXOPS];   // weights flat index l*4+i
};

__device__ float g_W[2][81];
__device__ int g_flag = 0;
__device__ int g_done = 0;

__global__ void __launch_bounds__(256)
qconv_fused(const float* __restrict__ x,
            const float* __restrict__ w1,
            const float* __restrict__ w2,
            float* __restrict__ out, Plan plan) {
    int t   = threadIdx.x;
    int bid = blockIdx.x;

    if (bid < 2) {
        // ================= builder (set = bid), R11-verified path ==========
        __shared__ float Ur[16][16], Ui[16][16];
        __shared__ float WA[81], WB[81];
        const float* w = bid ? w2 : w1;
        int col = t >> 4, amp = t & 15, lane = t & 31;

        float sr = (amp == col) ? 1.f : 0.f;
        float si = 0.f;
        for (int o = 0; o < plan.n; o++) {
            int ty = plan.type[o];
            if (ty == 3) {
                int bcb = 3 - plan.a[o], btb = 3 - plan.b[o];
                int src_amp  = amp ^ ((((amp >> bcb) & 1) ? 1 : 0) << btb);
                int src_lane = (lane & 16) | src_amp;
                sr = __shfl_sync(0xFFFFFFFFu, sr, src_lane);
                si = __shfl_sync(0xFFFFFFFFu, si, src_lane);
            } else {
                float th = w[plan.widx[o]];
                float c, s;
                __sincosf(0.5f * th, &s, &c);
                float a00r = c, a00i = 0.f, a01r = 0.f, a01i = 0.f;
                float a10r = 0.f, a10i = 0.f, a11r = c, a11i = 0.f;
                if (ty == 0)      { a01i = -s; a10i = -s; }      // RX
                else if (ty == 1) { a01r = -s; a10r =  s; }      // RY
                else              { a00i = -s; a11i =  s; }      // RZ
                int bitp = 3 - plan.a[o];
                int str  = 1 << bitp;
                float pr = __shfl_xor_sync(0xFFFFFFFFu, sr, str);
                float pi = __shfl_xor_sync(0xFFFFFFFFu, si, str);
                int bit = (amp >> bitp) & 1;
                float xr = bit ? pr : sr, xi = bit ? pi : si;
                float yr = bit ? sr : pr, yi = bit ? si : pi;
                float r0r = bit ? a10r : a00r, r0i = bit ? a10i : a00i;
                float r1r = bit ? a11r : a01r, r1i = bit ? a11i : a01i;
                sr = r0r * xr - r0i * xi + r1r * yr - r1i * yi;
                si = r0r * xi + r0i * xr + r1r * yi + r1i * yr;
            }
        }
        Ur[amp][col] = sr;
        Ui[amp][col] = si;
        if (t < 81) WA[t] = 0.f;
        __syncthreads();

        {
            int r = t >> 4, c = t & 15;
            float acc = 0.f;
            #pragma unroll
            for (int k = 0; k < 16; k++) {
                float z = (k & 8) ? -1.f : 1.f;
                acc += z * (Ur[k][r] * Ur[k][c] + Ui[k][r] * Ui[k][c]);
            }
            int m0 = ((r >> 3) & 1) + ((c >> 3) & 1);
            int m1 = ((r >> 2) & 1) + ((c >> 2) & 1);
            int m2 = ((r >> 1) & 1) + ((c >> 1) & 1);
            int m3 = (r & 1) + (c & 1);
            atomicAdd(&WA[((m0 * 3 + m1) * 3 + m2) * 3 + m3], acc);
        }

        #define XFORM(SRC, DST, S)                                            \
            __syncthreads();                                                  \
            if (t < 81) {                                                     \
                int n = (t / (S)) % 3;                                        \
                int base = t - n * (S);                                       \
                float i0 = SRC[base], i1 = SRC[base + (S)],                   \
                      i2 = SRC[base + 2 * (S)];                               \
                DST[t] = (n == 0) ? 0.5f * (i0 + i2)                          \
                       : (n == 1) ? 0.5f * (i0 - i2) : 0.5f * i1;             \
            }
        XFORM(WA, WB, 27)
        XFORM(WB, WA, 9)
        XFORM(WA, WB, 3)
        XFORM(WB, WA, 1)
        #undef XFORM

        __syncthreads();
        if (t < 81) g_W[bid][t] = WA[t];
        __threadfence();
        __syncthreads();
        if (t == 0) atomicAdd(&g_flag, 1);

    } else {
        // ================= compute (R9-verified eval) + own zero slices ====
        __shared__ float Wsh[2][81];
        __shared__ __align__(16) float tile[2][2][16][16];   // [set][slice][k][l]

        int cb    = bid - 2;
        int bc    = cb >> 3;   // b*16 + c
        int jg    = cb & 7;
        int slice = t >> 7;
        int k     = (t >> 3) & 15;
        int lq    = t & 7;
        int j     = 2 * jg + slice;

        const float* xb = x + (size_t)bc * 262144 + (size_t)(2 * j) * 4096
                            + (size_t)(2 * k) * 64 + 4 * lq;
        float4 v00 = *reinterpret_cast<const float4*>(xb);
        float4 v01 = *reinterpret_cast<const float4*>(xb + 64);
        float4 v10 = *reinterpret_cast<const float4*>(xb + 4096);
        float4 v11 = *reinterpret_cast<const float4*>(xb + 4096 + 64);

        int b = bc >> 4, c = bc & 15;

        // zero our share of the j>=16 half NOW (pre-wait work; 4 slices x 4KB)
        {
            const float4 z4 = make_float4(0.f, 0.f, 0.f, 0.f);
            #pragma unroll
            for (int s = 0; s < 2; s++)
                #pragma unroll
                for (int js = 0; js < 2; js++) {
                    float4* dst = reinterpret_cast<float4*>(
                        out + (size_t)b * 1048576 + (size_t)(c + 16 * s) * 32768
                            + (size_t)(16 + 2 * jg + js) * 1024);
                    dst[t] = z4;
                }
        }

        // per-point trig: CC/SS[p][dj][dk][dl], p = l parity (pre-wait work)
        const float PI_F = 3.14159265358979323846f;
        float CC[2][2][2][2], SS[2][2][2][2];
        {
            const float4* vv[2][2] = { { &v00, &v01 }, { &v10, &v11 } };
            #pragma unroll
            for (int dj = 0; dj < 2; dj++)
                #pragma unroll
                for (int dk = 0; dk < 2; dk++) {
                    float4 v = *vv[dj][dk];
                    float g[2][2] = { { v.x, v.y }, { v.z, v.w } };  // [p][dl]
                    #pragma unroll
                    for (int p = 0; p < 2; p++)
                        #pragma unroll
                        for (int dl = 0; dl < 2; dl++) {
                            float th2 = fminf(PI_F, PI_F * g[p][dl]);
                            __sincosf(th2, &SS[p][dj][dk][dl], &CC[p][dj][dk][dl]);
                        }
                }
        }

        // wait for builders, then stage W into shared
        if (t == 0) {
            while (*((volatile int*)&g_flag) < 2) __nanosleep(32);
            __threadfence();
        }
        __syncthreads();
        if (t < 162) ((float*)Wsh)[t] = ((const float*)g_W)[t];
        __syncthreads();

        #define MONO(M, Ca, Sa, Cb, Sb)                                       \
            { M[0] = 1.f;  M[1] = (Cb); M[2] = (Sb);                          \
              M[3] = (Ca); M[4] = (Ca) * (Cb); M[5] = (Ca) * (Sb);            \
              M[6] = (Sa); M[7] = (Sa) * (Cb); M[8] = (Sa) * (Sb); }

        float e[2][2];   // [set][p]
        #pragma unroll
        for (int s = 0; s < 2; s++) {
            float M01[2][9], M23[2][9];
            #pragma unroll
            for (int p = 0; p < 2; p++) {
                if (s == 0) {
                    // circuit 1: q = g(0,0,0), g(1,1,0), g(0,1,1), g(1,0,1)
                    MONO(M01[p], CC[p][0][0][0], SS[p][0][0][0],
                                 CC[p][1][1][0], SS[p][1][1][0]);
                    MONO(M23[p], CC[p][0][1][1], SS[p][0][1][1],
                                 CC[p][1][0][1], SS[p][1][0][1]);
                } else {
                    // circuit 2: q = g(1,1,1), g(0,0,1), g(1,0,0), g(0,1,0)
                    MONO(M01[p], CC[p][1][1][1], SS[p][1][1][1],
                                 CC[p][0][0][1], SS[p][0][0][1]);
                    MONO(M23[p], CC[p][1][0][0], SS[p][1][0][0],
                                 CC[p][0][1][0], SS[p][0][1][0]);
                }
            }
            float e0 = 0.f, e1 = 0.f;
            #pragma unroll
            for (int a = 0; a < 9; a++) {
                float t0 = 0.f, t1 = 0.f;
                #pragma unroll
                for (int bb = 0; bb < 9; bb++) {
                    float wv = Wsh[s][a * 9 + bb];    // one LDS serves 2 points
                    t0 = fmaf(wv, M23[0][bb], t0);
                    t1 = fmaf(wv, M23[1][bb], t1);
                }
                e0 = fmaf(M01[0][a], t0, e0);
                e1 = fmaf(M01[1][a], t1, e1);
            }
            e[s][0] = e0;
            e[s][1] = e1;
        }
        #undef MONO

        tile[0][slice][k][2 * lq]     = e[0][0];
        tile[0][slice][k][2 * lq + 1] = e[0][1];
        tile[1][slice][k][2 * lq]     = e[1][0];
        tile[1][slice][k][2 * lq + 1] = e[1][1];
        __syncthreads();

        // epilogue: 4 computed slices (2 sets x 2 j), zero-padded to 32x32
        int k2 = t >> 3;   // 0..31
        int q  = t & 7;    // float4 quad
        const float4 z4 = make_float4(0.f, 0.f, 0.f, 0.f);
        #pragma unroll
        for (int s = 0; s < 2; s++)
            #pragma unroll
            for (int js = 0; js < 2; js++) {
                float4 v = (k2 < 16 && q < 4)
                         ? reinterpret_cast<const float4*>(tile[s][js][k2])[q] : z4;
                float4* dst = reinterpret_cast<float4*>(
                    out + (size_t)b * 1048576 + (size_t)(c + 16 * s) * 32768
                        + (size_t)(2 * jg + js) * 1024);
                dst[t] = v;
            }
    }

    // ---- common tail: last block resets flag+counter for the next replay ----
    if (t == 0) {
        int old = atomicAdd(&g_done, 1);
        if (old == NBLOCKS - 1) {
            g_flag = 0;
            g_done = 0;
            __threadfence();
        }
    }
}

// ---------------------------------------------------------------------------
// Host: exact numpy default_rng(1234) plan generation (verified R3).
// ---------------------------------------------------------------------------
typedef unsigned __int128 u128;

struct NpRng {
    u128 state, inc;
    bool has32;
    uint32_t buf32;

    static u128 mult() {
        return ((u128)2549297995355413924ULL << 64) | 4865540595714422341ULL;
    }
    uint64_t next64() {
        state = state * mult() + inc;
        uint64_t hi = (uint64_t)(state >> 64);
        uint64_t lo = (uint64_t)state;
        unsigned rot = (unsigned)(state >> 122);
        uint64_t v = hi ^ lo;
        return (v >> rot) | (v << ((64u - rot) & 63u));
    }
    uint32_t next32() {
        if (has32) { has32 = false; return buf32; }
        uint64_t n = next64();
        has32 = true;
        buf32 = (uint32_t)(n >> 32);
        return (uint32_t)n;
    }
    double nextDouble() {
        return (double)(next64() >> 11) * (1.0 / 9007199254740992.0);
    }
    uint32_t lemire32(uint32_t rng) {
        uint32_t rng_excl = rng + 1u;
        uint64_t m = (uint64_t)next32() * (uint64_t)rng_excl;
        uint32_t leftover = (uint32_t)m;
        if (leftover < rng_excl) {
            uint32_t threshold = (uint32_t)((0xFFFFFFFFu - rng) % rng_excl);
            while (leftover < threshold) {
                m = (uint64_t)next32() * (uint64_t)rng_excl;
                leftover = (uint32_t)m;
            }
        }
        return (uint32_t)(m >> 32);
    }
};

static Plan make_plan_host() {
    const uint32_t INIT_A = 0x43b0d7e5u, MULT_A = 0x931e8875u;
    const uint32_t INIT_B = 0x8b51f9ddu, MULT_B = 0x58f38dedu;
    const uint32_t MIX_L  = 0xca01f9ddu, MIX_R  = 0x4973f715u;

    uint32_t pool[4];
    uint32_t hc = INIT_A;
    auto hashmix = [&](uint32_t v) -> uint32_t {
        v ^= hc; hc *= MULT_A; v *= hc; v ^= v >> 16; return v;
    };
    auto mixf = [&](uint32_t x, uint32_t y) -> uint32_t {
        uint32_t r = x * MIX_L - y * MIX_R; r ^= r >> 16; return r;
    };
    pool[0] = hashmix(1234u);
    pool[1] = hashmix(0u);
    pool[2] = hashmix(0u);
    pool[3] = hashmix(0u);
    for (int s = 0; s < 4; s++)
        for (int d = 0; d < 4; d++)
            if (s != d) pool[d] = mixf(pool[d], hashmix(pool[s]));

    uint32_t hb = INIT_B;
    uint32_t st32[8];
    for (int i = 0; i < 8; i++) {
        uint32_t dv = pool[i & 3];
        dv ^= hb; hb *= MULT_B; dv *= hb; dv ^= dv >> 16;
        st32[i] = dv;
    }
    uint64_t s64[4];
    for (int i = 0; i < 4; i++)
        s64[i] = (uint64_t)st32[2 * i] | ((uint64_t)st32[2 * i + 1] << 32);

    NpRng rng;
    u128 initstate = ((u128)s64[0] << 64) | s64[1];
    u128 initseq   = ((u128)s64[2] << 64) | s64[3];
    rng.inc   = (initseq << 1) | 1;
    rng.state = 0;
    rng.state = rng.state * NpRng::mult() + rng.inc;
    rng.state += initstate;
    rng.state = rng.state * NpRng::mult() + rng.inc;
    rng.has32 = false;
    rng.buf32 = 0;

    Plan plan;
    plan.n = 0;
    for (int l = 0; l < 2; l++) {
        int i = 0;
        while (i < 4 && plan.n < MAXOPS) {
            if (rng.nextDouble() > 0.3) {
                int g = (int)rng.lemire32(2);
                int w = (int)rng.lemire32(3);
                plan.type[plan.n] = g;
                plan.a[plan.n]    = w;
                plan.b[plan.n]    = 0;
                plan.widx[plan.n] = l * 4 + i;
                plan.n++;
                i++;
            } else {
                uint64_t hash_set[4] = { ~0ULL, ~0ULL, ~0ULL, ~0ULL };
                int64_t idx[2];
                for (int jf = 2; jf <= 3; jf++) {
                    uint64_t val = (uint64_t)rng.lemire32((uint32_t)jf);
                    uint64_t loc = val & 3;
                    while (hash_set[loc] != ~0ULL && hash_set[loc] != val)
                        loc = (loc + 1) & 3;
                    if (hash_set[loc] == ~0ULL) {
                        hash_set[loc] = val;
                        idx[jf - 2] = (int64_t)val;
                    } else {
                        loc = (uint64_t)jf & 3;
                        while (hash_set[loc] != ~0ULL) loc = (loc + 1) & 3;
                        hash_set[loc] = (uint64_t)jf;
                        idx[jf - 2] = jf;
                    }
                }
                uint32_t sh = rng.lemire32(1u);   // Lemire-32 (top bit)
                int64_t tmp = idx[1]; idx[1] = idx[sh]; idx[sh] = tmp;

                plan.type[plan.n] = 3;
                plan.a[plan.n]    = (int)idx[0];
                plan.b[plan.n]    = (int)idx[1];
                plan.widx[plan.n] = 0;
                plan.n++;
            }
        }
    }
    return plan;
}

// ---------------------------------------------------------------------------
extern "C" void kernel_launch(void* const* d_in, const int* in_sizes, int n_in,
                              void* d_out, int out_size) {
    const float* x  = (const float*)d_in[0];
    const float* w1 = (const float*)d_in[1];
    const float* w2 = (const float*)d_in[2];
    float* out = (float*)d_out;

    Plan plan = make_plan_host();

    qconv_fused<<<NBLOCKS, 256>>>(x, w1, w2, out, plan);
}

// round 15
// speedup vs baseline: 1.1569x; 1.1569x over previous
#include <cuda_runtime.h>
#include <cstdint>
#include <math.h>

// ---------------------------------------------------------------------------
//   x: [4,16,64,64,64] f32    weights1/2: [2,4] f32    out: [4,32,32,32,32] f32
// <Z0> = v^T S v  ->  81 coeffs in double-angle basis (1, cos2a, sin2a),
// 2a = min(pi, pi*y). Two kernels (fused/spin family falsified R10-R14):
//   build_W: 2x256, warp-shuffle sim -> g_W
//   main:    1280 x 128 threads:
//     [0,1024):    compute one (bc, j) slice, 2 l-points/thread,
//                  W rows read as float4 (LDS.128) from padded shared
//     [1024,1280): zero-fill j>=16 half (32KB per block)
// ---------------------------------------------------------------------------

#define MAXOPS 64

struct Plan {
    int n;
    int type[MAXOPS];   // 0=RX, 1=RY, 2=RZ, 3=CNOT
    int a[MAXOPS];      // rot wire, or cnot control
    int b[MAXOPS];      // cnot target
    int widx[MAXOPS];   // weights flat index l*4+i
};

__device__ float g_W[2][81];

// ---------------------------------------------------------------------------
// Prelude (verified R9/R13): warp-shuffle circuit sim, bin, basis-change.
// ---------------------------------------------------------------------------
__global__ void build_W_kernel(const float* __restrict__ w1,
                               const float* __restrict__ w2,
                               Plan plan) {
    __shared__ float Ur[16][16], Ui[16][16];
    __shared__ float WA[81], WB[81];
    const float* w = (blockIdx.x == 0) ? w1 : w2;
    int t    = threadIdx.x;
    int col  = t >> 4;
    int amp  = t & 15;
    int lane = t & 31;

    float sr = (amp == col) ? 1.f : 0.f;
    float si = 0.f;

    for (int o = 0; o < plan.n; o++) {
        int ty = plan.type[o];
        if (ty == 3) {
            int bcb = 3 - plan.a[o], btb = 3 - plan.b[o];
            int src_amp  = amp ^ ((((amp >> bcb) & 1) ? 1 : 0) << btb);
            int src_lane = (lane & 16) | src_amp;
            sr = __shfl_sync(0xFFFFFFFFu, sr, src_lane);
            si = __shfl_sync(0xFFFFFFFFu, si, src_lane);
        } else {
            float th = w[plan.widx[o]];
            float c, s;
            __sincosf(0.5f * th, &s, &c);
            float a00r = c, a00i = 0.f, a01r = 0.f, a01i = 0.f;
            float a10r = 0.f, a10i = 0.f, a11r = c, a11i = 0.f;
            if (ty == 0)      { a01i = -s; a10i = -s; }      // RX
            else if (ty == 1) { a01r = -s; a10r =  s; }      // RY
            else              { a00i = -s; a11i =  s; }      // RZ
            int bitp = 3 - plan.a[o];
            int str  = 1 << bitp;
            float pr = __shfl_xor_sync(0xFFFFFFFFu, sr, str);
            float pi = __shfl_xor_sync(0xFFFFFFFFu, si, str);
            int bit = (amp >> bitp) & 1;
            float xr = bit ? pr : sr, xi = bit ? pi : si;
            float yr = bit ? sr : pr, yi = bit ? si : pi;
            float r0r = bit ? a10r : a00r, r0i = bit ? a10i : a00i;
            float r1r = bit ? a11r : a01r, r1i = bit ? a11i : a01i;
            sr = r0r * xr - r0i * xi + r1r * yr - r1i * yi;
            si = r0r * xi + r0i * xr + r1r * yi + r1i * yr;
        }
    }
    Ur[amp][col] = sr;
    Ui[amp][col] = si;
    if (t < 81) WA[t] = 0.f;
    __syncthreads();

    {
        int r = t >> 4, c = t & 15;
        float acc = 0.f;
        #pragma unroll
        for (int k = 0; k < 16; k++) {
            float z = (k & 8) ? -1.f : 1.f;
            acc += z * (Ur[k][r] * Ur[k][c] + Ui[k][r] * Ui[k][c]);
        }
        int m0 = ((r >> 3) & 1) + ((c >> 3) & 1);
        int m1 = ((r >> 2) & 1) + ((c >> 2) & 1);
        int m2 = ((r >> 1) & 1) + ((c >> 1) & 1);
        int m3 = (r & 1) + (c & 1);
        atomicAdd(&WA[((m0 * 3 + m1) * 3 + m2) * 3 + m3], acc);
    }

    #define XFORM(SRC, DST, S)                                            \
        __syncthreads();                                                  \
        if (t < 81) {                                                     \
            int n = (t / (S)) % 3;                                        \
            int base = t - n * (S);                                       \
            float i0 = SRC[base], i1 = SRC[base + (S)], i2 = SRC[base + 2 * (S)]; \
            DST[t] = (n == 0) ? 0.5f * (i0 + i2)                          \
                   : (n == 1) ? 0.5f * (i0 - i2) : 0.5f * i1;             \
        }
    XFORM(WA, WB, 27)
    XFORM(WB, WA, 9)
    XFORM(WA, WB, 3)
    XFORM(WB, WA, 1)
    #undef XFORM

    __syncthreads();
    if (t < 81) g_W[blockIdx.x][t] = WA[t];
}

// ---------------------------------------------------------------------------
// Main kernel: 1280 blocks x 128 threads.
// ---------------------------------------------------------------------------
__global__ void __launch_bounds__(128)
qconv_main_kernel(const float* __restrict__ x, float* __restrict__ out) {
    int t = threadIdx.x;

    if (blockIdx.x >= 1024) {
        // zero-fill: zi in [0,256), each covers 32KB of the j>=16 half
        int zi = blockIdx.x - 1024;
        int b    = zi >> 6;
        int ch   = (zi >> 1) & 31;
        int half = zi & 1;
        float4* dst = reinterpret_cast<float4*>(
            out + (size_t)b * 1048576 + (size_t)ch * 32768
                + 16384 + (size_t)half * 8192);
        const float4 z4 = make_float4(0.f, 0.f, 0.f, 0.f);
        #pragma unroll
        for (int r = 0; r < 16; r++) dst[t + 128 * r] = z4;
        return;
    }

    // Padded W: rows of 12 floats (9 used), 16B-aligned rows -> LDS.128 reads
    __shared__ __align__(16) float Wsh[2][9][12];
    __shared__ __align__(16) float tile[2][16][16];   // [set][k][l]

    int bc = blockIdx.x >> 4;    // b*16 + c
    int j  = blockIdx.x & 15;
    int k  = t >> 3;             // 0..15
    int lq = t & 7;              // float4 quad: points l = 2lq, 2lq+1

    const float* xb = x + (size_t)bc * 262144 + (size_t)(2 * j) * 4096
                        + (size_t)(2 * k) * 64 + 4 * lq;
    float4 v00 = *reinterpret_cast<const float4*>(xb);
    float4 v01 = *reinterpret_cast<const float4*>(xb + 64);
    float4 v10 = *reinterpret_cast<const float4*>(xb + 4096);
    float4 v11 = *reinterpret_cast<const float4*>(xb + 4096 + 64);

    // stage W (padded): 216 slots, 128 threads -> 2 rounds
    #pragma unroll
    for (int i = 0; i < 2; i++) {
        int idx = t + 128 * i;
        if (idx < 216) {
            int s   = idx / 108;
            int rem = idx % 108;
            int a   = rem / 12;
            int col = rem % 12;
            Wsh[s][a][col] = (col < 9) ? g_W[s][a * 9 + col] : 0.f;
        }
    }

    // per-point trig: CC/SS[p][dj][dk][dl], p = l parity
    const float PI_F = 3.14159265358979323846f;
    float CC[2][2][2][2], SS[2][2][2][2];
    {
        const float4* vv[2][2] = { { &v00, &v01 }, { &v10, &v11 } };
        #pragma unroll
        for (int dj = 0; dj < 2; dj++)
            #pragma unroll
            for (int dk = 0; dk < 2; dk++) {
                float4 v = *vv[dj][dk];
                float g[2][2] = { { v.x, v.y }, { v.z, v.w } };  // [p][dl]
                #pragma unroll
                for (int p = 0; p < 2; p++)
                    #pragma unroll
                    for (int dl = 0; dl < 2; dl++) {
                        float th2 = fminf(PI_F, PI_F * g[p][dl]);
                        __sincosf(th2, &SS[p][dj][dk][dl], &CC[p][dj][dk][dl]);
                    }
            }
    }

    __syncthreads();   // Wsh ready

    #define MONO(M, Ca, Sa, Cb, Sb)                                       \
        { M[0] = 1.f;  M[1] = (Cb); M[2] = (Sb);                          \
          M[3] = (Ca); M[4] = (Ca) * (Cb); M[5] = (Ca) * (Sb);            \
          M[6] = (Sa); M[7] = (Sa) * (Cb); M[8] = (Sa) * (Sb); }

    float e[2][2];   // [set][p]
    #pragma unroll
    for (int s = 0; s < 2; s++) {
        float M01[2][9], M23[2][9];
        #pragma unroll
        for (int p = 0; p < 2; p++) {
            if (s == 0) {
                // circuit 1: q = g(0,0,0), g(1,1,0), g(0,1,1), g(1,0,1)
                MONO(M01[p], CC[p][0][0][0], SS[p][0][0][0],
                             CC[p][1][1][0], SS[p][1][1][0]);
                MONO(M23[p], CC[p][0][1][1], SS[p][0][1][1],
                             CC[p][1][0][1], SS[p][1][0][1]);
            } else {
                // circuit 2: q = g(1,1,1), g(0,0,1), g(1,0,0), g(0,1,0)
                MONO(M01[p], CC[p][1][1][1], SS[p][1][1][1],
                             CC[p][0][0][1], SS[p][0][0][1]);
                MONO(M23[p], CC[p][1][0][0], SS[p][1][0][0],
                             CC[p][0][1][0], SS[p][0][1][0]);
            }
        }
        float e0 = 0.f, e1 = 0.f;
        #pragma unroll
        for (int a = 0; a < 9; a++) {
            // 9-float W row via 2x LDS.128 + 1x LDS.32 (rows 48B, 16B aligned)
            float4 wA = *reinterpret_cast<const float4*>(&Wsh[s][a][0]);
            float4 wB = *reinterpret_cast<const float4*>(&Wsh[s][a][4]);
            float  w8 = Wsh[s][a][8];
            float t0, t1;
            t0 = wA.x * M23[0][0];                 t1 = wA.x * M23[1][0];
            t0 = fmaf(wA.y, M23[0][1], t0);        t1 = fmaf(wA.y, M23[1][1], t1);
            t0 = fmaf(wA.z, M23[0][2], t0);        t1 = fmaf(wA.z, M23[1][2], t1);
            t0 = fmaf(wA.w, M23[0][3], t0);        t1 = fmaf(wA.w, M23[1][3], t1);
            t0 = fmaf(wB.x, M23[0][4], t0);        t1 = fmaf(wB.x, M23[1][4], t1);
            t0 = fmaf(wB.y, M23[0][5], t0);        t1 = fmaf(wB.y, M23[1][5], t1);
            t0 = fmaf(wB.z, M23[0][6], t0);        t1 = fmaf(wB.z, M23[1][6], t1);
            t0 = fmaf(wB.w, M23[0][7], t0);        t1 = fmaf(wB.w, M23[1][7], t1);
            t0 = fmaf(w8,   M23[0][8], t0);        t1 = fmaf(w8,   M23[1][8], t1);
            e0 = fmaf(M01[0][a], t0, e0);
            e1 = fmaf(M01[1][a], t1, e1);
        }
        e[s][0] = e0;
        e[s][1] = e1;
    }
    #undef MONO

    tile[0][k][2 * lq]     = e[0][0];
    tile[0][k][2 * lq + 1] = e[0][1];
    tile[1][k][2 * lq]     = e[1][0];
    tile[1][k][2 * lq + 1] = e[1][1];
    __syncthreads();

    // epilogue: 2 output slices (set 0/1 of this j), zero-padded to 32x32
    int b = bc >> 4, c = bc & 15;
    const float4 z4 = make_float4(0.f, 0.f, 0.f, 0.f);
    #pragma unroll
    for (int s = 0; s < 2; s++) {
        float4* dst = reinterpret_cast<float4*>(
            out + (size_t)b * 1048576 + (size_t)(c + 16 * s) * 32768
                + (size_t)j * 1024);
        #pragma unroll
        for (int r = 0; r < 2; r++) {
            int idx = t + 128 * r;       // 0..255 float4 slots of the slice
            int k2  = idx >> 3;
            int q   = idx & 7;
            float4 v = (k2 < 16 && q < 4)
                     ? reinterpret_cast<const float4*>(tile[s][k2])[q] : z4;
            dst[idx] = v;
        }
    }
}

// ---------------------------------------------------------------------------
// Host: exact numpy default_rng(1234) plan generation (verified R3).
// ---------------------------------------------------------------------------
typedef unsigned __int128 u128;

struct NpRng {
    u128 state, inc;
    bool has32;
    uint32_t buf32;

    static u128 mult() {
        return ((u128)2549297995355413924ULL << 64) | 4865540595714422341ULL;
    }
    uint64_t next64() {
        state = state * mult() + inc;
        uint64_t hi = (uint64_t)(state >> 64);
        uint64_t lo = (uint64_t)state;
        unsigned rot = (unsigned)(state >> 122);
        uint64_t v = hi ^ lo;
        return (v >> rot) | (v << ((64u - rot) & 63u));
    }
    uint32_t next32() {
        if (has32) { has32 = false; return buf32; }
        uint64_t n = next64();
        has32 = true;
        buf32 = (uint32_t)(n >> 32);
        return (uint32_t)n;
    }
    double nextDouble() {
        return (double)(next64() >> 11) * (1.0 / 9007199254740992.0);
    }
    uint32_t lemire32(uint32_t rng) {
        uint32_t rng_excl = rng + 1u;
        uint64_t m = (uint64_t)next32() * (uint64_t)rng_excl;
        uint32_t leftover = (uint32_t)m;
        if (leftover < rng_excl) {
            uint32_t threshold = (uint32_t)((0xFFFFFFFFu - rng) % rng_excl);
            while (leftover < threshold) {
                m = (uint64_t)next32() * (uint64_t)rng_excl;
                leftover = (uint32_t)m;
            }
        }
        return (uint32_t)(m >> 32);
    }
};

static Plan make_plan_host() {
    const uint32_t INIT_A = 0x43b0d7e5u, MULT_A = 0x931e8875u;
    const uint32_t INIT_B = 0x8b51f9ddu, MULT_B = 0x58f38dedu;
    const uint32_t MIX_L  = 0xca01f9ddu, MIX_R  = 0x4973f715u;

    uint32_t pool[4];
    uint32_t hc = INIT_A;
    auto hashmix = [&](uint32_t v) -> uint32_t {
        v ^= hc; hc *= MULT_A; v *= hc; v ^= v >> 16; return v;
    };
    auto mixf = [&](uint32_t x, uint32_t y) -> uint32_t {
        uint32_t r = x * MIX_L - y * MIX_R; r ^= r >> 16; return r;
    };
    pool[0] = hashmix(1234u);
    pool[1] = hashmix(0u);
    pool[2] = hashmix(0u);
    pool[3] = hashmix(0u);
    for (int s = 0; s < 4; s++)
        for (int d = 0; d < 4; d++)
            if (s != d) pool[d] = mixf(pool[d], hashmix(pool[s]));

    uint32_t hb = INIT_B;
    uint32_t st32[8];
    for (int i = 0; i < 8; i++) {
        uint32_t dv = pool[i & 3];
        dv ^= hb; hb *= MULT_B; dv *= hb; dv ^= dv >> 16;
        st32[i] = dv;
    }
    uint64_t s64[4];
    for (int i = 0; i < 4; i++)
        s64[i] = (uint64_t)st32[2 * i] | ((uint64_t)st32[2 * i + 1] << 32);

    NpRng rng;
    u128 initstate = ((u128)s64[0] << 64) | s64[1];
    u128 initseq   = ((u128)s64[2] << 64) | s64[3];
    rng.inc   = (initseq << 1) | 1;
    rng.state = 0;
    rng.state = rng.state * NpRng::mult() + rng.inc;
    rng.state += initstate;
    rng.state = rng.state * NpRng::mult() + rng.inc;
    rng.has32 = false;
    rng.buf32 = 0;

    Plan plan;
    plan.n = 0;
    for (int l = 0; l < 2; l++) {
        int i = 0;
        while (i < 4 && plan.n < MAXOPS) {
            if (rng.nextDouble() > 0.3) {
                int g = (int)rng.lemire32(2);
                int w = (int)rng.lemire32(3);
                plan.type[plan.n] = g;
                plan.a[plan.n]    = w;
                plan.b[plan.n]    = 0;
                plan.widx[plan.n] = l * 4 + i;
                plan.n++;
                i++;
            } else {
                uint64_t hash_set[4] = { ~0ULL, ~0ULL, ~0ULL, ~0ULL };
                int64_t idx[2];
                for (int jf = 2; jf <= 3; jf++) {
                    uint64_t val = (uint64_t)rng.lemire32((uint32_t)jf);
                    uint64_t loc = val & 3;
                    while (hash_set[loc] != ~0ULL && hash_set[loc] != val)
                        loc = (loc + 1) & 3;
                    if (hash_set[loc] == ~0ULL) {
                        hash_set[loc] = val;
                        idx[jf - 2] = (int64_t)val;
                    } else {
                        loc = (uint64_t)jf & 3;
                        while (hash_set[loc] != ~0ULL) loc = (loc + 1) & 3;
                        hash_set[loc] = (uint64_t)jf;
                        idx[jf - 2] = jf;
                    }
                }
                uint32_t sh = rng.lemire32(1u);   // Lemire-32 (top bit)
                int64_t tmp = idx[1]; idx[1] = idx[sh]; idx[sh] = tmp;

                plan.type[plan.n] = 3;
                plan.a[plan.n]    = (int)idx[0];
                plan.b[plan.n]    = (int)idx[1];
                plan.widx[plan.n] = 0;
                plan.n++;
            }
        }
    }
    return plan;
}

// ---------------------------------------------------------------------------
extern "C" void kernel_launch(void* const* d_in, const int* in_sizes, int n_in,
                              void* d_out, int out_size) {
    const float* x  = (const float*)d_in[0];
    const float* w1 = (const float*)d_in[1];
    const float* w2 = (const float*)d_in[2];
    float* out = (float*)d_out;

    Plan plan = make_plan_host();

    build_W_kernel<<<2, 256>>>(w1, w2, plan);
    qconv_main_kernel<<<1280, 128>>>(x, out);
}

// round 16
// speedup vs baseline: 1.1830x; 1.0226x over previous
#include <cuda_runtime.h>
#include <cstdint>
#include <math.h>

// ---------------------------------------------------------------------------
//   x: [4,16,64,64,64] f32    weights1/2: [2,4] f32    out: [4,32,32,32,32] f32
// <Z0> = v^T S v  ->  81 coeffs in double-angle basis (1, cos2a, sin2a),
// 2a = min(pi, pi*y). Two kernels:
//   build_W: 2x256, warp-shuffle sim -> g_W
//   main:    1280 x 128 threads:
//     [0,1024):    compute one (bc, j) slice, 2 l-points/thread,
//                  W rows via LDS.128; DIRECT epilogue stores (no tile/sync)
//     [1024,1280): zero-fill j>=16 half (32KB per block)
// ---------------------------------------------------------------------------

#define MAXOPS 64

struct Plan {
    int n;
    int type[MAXOPS];   // 0=RX, 1=RY, 2=RZ, 3=CNOT
    int a[MAXOPS];      // rot wire, or cnot control
    int b[MAXOPS];      // cnot target
    int widx[MAXOPS];   // weights flat index l*4+i
};

__device__ float g_W[2][81];

// ---------------------------------------------------------------------------
// Prelude (verified R9/R13): warp-shuffle circuit sim, bin, basis-change.
// ---------------------------------------------------------------------------
__global__ void build_W_kernel(const float* __restrict__ w1,
                               const float* __restrict__ w2,
                               Plan plan) {
    __shared__ float Ur[16][16], Ui[16][16];
    __shared__ float WA[81], WB[81];
    const float* w = (blockIdx.x == 0) ? w1 : w2;
    int t    = threadIdx.x;
    int col  = t >> 4;
    int amp  = t & 15;
    int lane = t & 31;

    float sr = (amp == col) ? 1.f : 0.f;
    float si = 0.f;

    for (int o = 0; o < plan.n; o++) {
        int ty = plan.type[o];
        if (ty == 3) {
            int bcb = 3 - plan.a[o], btb = 3 - plan.b[o];
            int src_amp  = amp ^ ((((amp >> bcb) & 1) ? 1 : 0) << btb);
            int src_lane = (lane & 16) | src_amp;
            sr = __shfl_sync(0xFFFFFFFFu, sr, src_lane);
            si = __shfl_sync(0xFFFFFFFFu, si, src_lane);
        } else {
            float th = w[plan.widx[o]];
            float c, s;
            __sincosf(0.5f * th, &s, &c);
            float a00r = c, a00i = 0.f, a01r = 0.f, a01i = 0.f;
            float a10r = 0.f, a10i = 0.f, a11r = c, a11i = 0.f;
            if (ty == 0)      { a01i = -s; a10i = -s; }      // RX
            else if (ty == 1) { a01r = -s; a10r =  s; }      // RY
            else              { a00i = -s; a11i =  s; }      // RZ
            int bitp = 3 - plan.a[o];
            int str  = 1 << bitp;
            float pr = __shfl_xor_sync(0xFFFFFFFFu, sr, str);
            float pi = __shfl_xor_sync(0xFFFFFFFFu, si, str);
            int bit = (amp >> bitp) & 1;
            float xr = bit ? pr : sr, xi = bit ? pi : si;
            float yr = bit ? sr : pr, yi = bit ? si : pi;
            float r0r = bit ? a10r : a00r, r0i = bit ? a10i : a00i;
            float r1r = bit ? a11r : a01r, r1i = bit ? a11i : a01i;
            sr = r0r * xr - r0i * xi + r1r * yr - r1i * yi;
            si = r0r * xi + r0i * xr + r1r * yi + r1i * yr;
        }
    }
    Ur[amp][col] = sr;
    Ui[amp][col] = si;
    if (t < 81) WA[t] = 0.f;
    __syncthreads();

    {
        int r = t >> 4, c = t & 15;
        float acc = 0.f;
        #pragma unroll
        for (int k = 0; k < 16; k++) {
            float z = (k & 8) ? -1.f : 1.f;
            acc += z * (Ur[k][r] * Ur[k][c] + Ui[k][r] * Ui[k][c]);
        }
        int m0 = ((r >> 3) & 1) + ((c >> 3) & 1);
        int m1 = ((r >> 2) & 1) + ((c >> 2) & 1);
        int m2 = ((r >> 1) & 1) + ((c >> 1) & 1);
        int m3 = (r & 1) + (c & 1);
        atomicAdd(&WA[((m0 * 3 + m1) * 3 + m2) * 3 + m3], acc);
    }

    #define XFORM(SRC, DST, S)                                            \
        __syncthreads();                                                  \
        if (t < 81) {                                                     \
            int n = (t / (S)) % 3;                                        \
            int base = t - n * (S);                                       \
            float i0 = SRC[base], i1 = SRC[base + (S)], i2 = SRC[base + 2 * (S)]; \
            DST[t] = (n == 0) ? 0.5f * (i0 + i2)                          \
                   : (n == 1) ? 0.5f * (i0 - i2) : 0.5f * i1;             \
        }
    XFORM(WA, WB, 27)
    XFORM(WB, WA, 9)
    XFORM(WA, WB, 3)
    XFORM(WB, WA, 1)
    #undef XFORM

    __syncthreads();
    if (t < 81) g_W[blockIdx.x][t] = WA[t];
}

// ---------------------------------------------------------------------------
// Main kernel: 1280 blocks x 128 threads.
// ---------------------------------------------------------------------------
__global__ void __launch_bounds__(128)
qconv_main_kernel(const float* __restrict__ x, float* __restrict__ out) {
    int t = threadIdx.x;

    if (blockIdx.x >= 1024) {
        // zero-fill: zi in [0,256), each covers 32KB of the j>=16 half
        int zi = blockIdx.x - 1024;
        int b    = zi >> 6;
        int ch   = (zi >> 1) & 31;
        int half = zi & 1;
        float4* dst = reinterpret_cast<float4*>(
            out + (size_t)b * 1048576 + (size_t)ch * 32768
                + 16384 + (size_t)half * 8192);
        const float4 z4 = make_float4(0.f, 0.f, 0.f, 0.f);
        #pragma unroll
        for (int r = 0; r < 16; r++) dst[t + 128 * r] = z4;
        return;
    }

    // Padded W: rows of 12 floats (9 used), 16B-aligned rows -> LDS.128 reads
    __shared__ __align__(16) float Wsh[2][9][12];

    int bc = blockIdx.x >> 4;    // b*16 + c
    int j  = blockIdx.x & 15;
    int k  = t >> 3;             // 0..15
    int lq = t & 7;              // float4 quad: points l = 2lq, 2lq+1

    const float* xb = x + (size_t)bc * 262144 + (size_t)(2 * j) * 4096
                        + (size_t)(2 * k) * 64 + 4 * lq;
    float4 v00 = *reinterpret_cast<const float4*>(xb);
    float4 v01 = *reinterpret_cast<const float4*>(xb + 64);
    float4 v10 = *reinterpret_cast<const float4*>(xb + 4096);
    float4 v11 = *reinterpret_cast<const float4*>(xb + 4096 + 64);

    // stage W (padded): 216 slots, 128 threads -> 2 rounds
    #pragma unroll
    for (int i = 0; i < 2; i++) {
        int idx = t + 128 * i;
        if (idx < 216) {
            int s   = idx / 108;
            int rem = idx % 108;
            int a   = rem / 12;
            int col = rem % 12;
            Wsh[s][a][col] = (col < 9) ? g_W[s][a * 9 + col] : 0.f;
        }
    }

    // per-point trig: CC/SS[p][dj][dk][dl], p = l parity
    const float PI_F = 3.14159265358979323846f;
    float CC[2][2][2][2], SS[2][2][2][2];
    {
        const float4* vv[2][2] = { { &v00, &v01 }, { &v10, &v11 } };
        #pragma unroll
        for (int dj = 0; dj < 2; dj++)
            #pragma unroll
            for (int dk = 0; dk < 2; dk++) {
                float4 v = *vv[dj][dk];
                float g[2][2] = { { v.x, v.y }, { v.z, v.w } };  // [p][dl]
                #pragma unroll
                for (int p = 0; p < 2; p++)
                    #pragma unroll
                    for (int dl = 0; dl < 2; dl++) {
                        float th2 = fminf(PI_F, PI_F * g[p][dl]);
                        __sincosf(th2, &SS[p][dj][dk][dl], &CC[p][dj][dk][dl]);
                    }
            }
    }

    __syncthreads();   // Wsh ready

    #define MONO(M, Ca, Sa, Cb, Sb)                                       \
        { M[0] = 1.f;  M[1] = (Cb); M[2] = (Sb);                          \
          M[3] = (Ca); M[4] = (Ca) * (Cb); M[5] = (Ca) * (Sb);            \
          M[6] = (Sa); M[7] = (Sa) * (Cb); M[8] = (Sa) * (Sb); }

    float e[2][2];   // [set][p]
    #pragma unroll
    for (int s = 0; s < 2; s++) {
        float M01[2][9], M23[2][9];
        #pragma unroll
        for (int p = 0; p < 2; p++) {
            if (s == 0) {
                // circuit 1: q = g(0,0,0), g(1,1,0), g(0,1,1), g(1,0,1)
                MONO(M01[p], CC[p][0][0][0], SS[p][0][0][0],
                             CC[p][1][1][0], SS[p][1][1][0]);
                MONO(M23[p], CC[p][0][1][1], SS[p][0][1][1],
                             CC[p][1][0][1], SS[p][1][0][1]);
            } else {
                // circuit 2: q = g(1,1,1), g(0,0,1), g(1,0,0), g(0,1,0)
                MONO(M01[p], CC[p][1][1][1], SS[p][1][1][1],
                             CC[p][0][0][1], SS[p][0][0][1]);
                MONO(M23[p], CC[p][1][0][0], SS[p][1][0][0],
                             CC[p][0][1][0], SS[p][0][1][0]);
            }
        }
        float e0 = 0.f, e1 = 0.f;
        #pragma unroll
        for (int a = 0; a < 9; a++) {
            // 9-float W row via 2x LDS.128 + 1x LDS.32 (rows 48B, 16B aligned)
            float4 wA = *reinterpret_cast<const float4*>(&Wsh[s][a][0]);
            float4 wB = *reinterpret_cast<const float4*>(&Wsh[s][a][4]);
            float  w8 = Wsh[s][a][8];
            float t0, t1;
            t0 = wA.x * M23[0][0];                 t1 = wA.x * M23[1][0];
            t0 = fmaf(wA.y, M23[0][1], t0);        t1 = fmaf(wA.y, M23[1][1], t1);
            t0 = fmaf(wA.z, M23[0][2], t0);        t1 = fmaf(wA.z, M23[1][2], t1);
            t0 = fmaf(wA.w, M23[0][3], t0);        t1 = fmaf(wA.w, M23[1][3], t1);
            t0 = fmaf(wB.x, M23[0][4], t0);        t1 = fmaf(wB.x, M23[1][4], t1);
            t0 = fmaf(wB.y, M23[0][5], t0);        t1 = fmaf(wB.y, M23[1][5], t1);
            t0 = fmaf(wB.z, M23[0][6], t0);        t1 = fmaf(wB.z, M23[1][6], t1);
            t0 = fmaf(wB.w, M23[0][7], t0);        t1 = fmaf(wB.w, M23[1][7], t1);
            t0 = fmaf(w8,   M23[0][8], t0);        t1 = fmaf(w8,   M23[1][8], t1);
            e0 = fmaf(M01[0][a], t0, e0);
            e1 = fmaf(M01[1][a], t1, e1);
        }
        e[s][0] = e0;
        e[s][1] = e1;
    }
    #undef MONO

    // ---- DIRECT epilogue: each thread stores its own outputs + zero shares.
    // Per set slice (32x32): computed float2 at (k, 2lq); zero float2 at
    // (k, 16+2lq); rows 16..31 = 128 float4, one per thread.
    int b = bc >> 4, c = bc & 15;
    const float2 z2 = make_float2(0.f, 0.f);
    const float4 z4 = make_float4(0.f, 0.f, 0.f, 0.f);
    int zrow = 16 + (t >> 3);
    int zcol = 4 * (t & 7);
    #pragma unroll
    for (int s = 0; s < 2; s++) {
        float* base = out + (size_t)b * 1048576 + (size_t)(c + 16 * s) * 32768
                          + (size_t)j * 1024;
        *reinterpret_cast<float2*>(base + k * 32 + 2 * lq)      =
            make_float2(e[s][0], e[s][1]);
        *reinterpret_cast<float2*>(base + k * 32 + 16 + 2 * lq) = z2;
        *reinterpret_cast<float4*>(base + zrow * 32 + zcol)     = z4;
    }
}

// ---------------------------------------------------------------------------
// Host: exact numpy default_rng(1234) plan generation (verified R3).
// ---------------------------------------------------------------------------
typedef unsigned __int128 u128;

struct NpRng {
    u128 state, inc;
    bool has32;
    uint32_t buf32;

    static u128 mult() {
        return ((u128)2549297995355413924ULL << 64) | 4865540595714422341ULL;
    }
    uint64_t next64() {
        state = state * mult() + inc;
        uint64_t hi = (uint64_t)(state >> 64);
        uint64_t lo = (uint64_t)state;
        unsigned rot = (unsigned)(state >> 122);
        uint64_t v = hi ^ lo;
        return (v >> rot) | (v << ((64u - rot) & 63u));
    }
    uint32_t next32() {
        if (has32) { has32 = false; return buf32; }
        uint64_t n = next64();
        has32 = true;
        buf32 = (uint32_t)(n >> 32);
        return (uint32_t)n;
    }
    double nextDouble() {
        return (double)(next64() >> 11) * (1.0 / 9007199254740992.0);
    }
    uint32_t lemire32(uint32_t rng) {
        uint32_t rng_excl = rng + 1u;
        uint64_t m = (uint64_t)next32() * (uint64_t)rng_excl;
        uint32_t leftover = (uint32_t)m;
        if (leftover < rng_excl) {
            uint32_t threshold = (uint32_t)((0xFFFFFFFFu - rng) % rng_excl);
            while (leftover < threshold) {
                m = (uint64_t)next32() * (uint64_t)rng_excl;
                leftover = (uint32_t)m;
            }
        }
        return (uint32_t)(m >> 32);
    }
};

static Plan make_plan_host() {
    const uint32_t INIT_A = 0x43b0d7e5u, MULT_A = 0x931e8875u;
    const uint32_t INIT_B = 0x8b51f9ddu, MULT_B = 0x58f38dedu;
    const uint32_t MIX_L  = 0xca01f9ddu, MIX_R  = 0x4973f715u;

    uint32_t pool[4];
    uint32_t hc = INIT_A;
    auto hashmix = [&](uint32_t v) -> uint32_t {
        v ^= hc; hc *= MULT_A; v *= hc; v ^= v >> 16; return v;
    };
    auto mixf = [&](uint32_t x, uint32_t y) -> uint32_t {
        uint32_t r = x * MIX_L - y * MIX_R; r ^= r >> 16; return r;
    };
    pool[0] = hashmix(1234u);
    pool[1] = hashmix(0u);
    pool[2] = hashmix(0u);
    pool[3] = hashmix(0u);
    for (int s = 0; s < 4; s++)
        for (int d = 0; d < 4; d++)
            if (s != d) pool[d] = mixf(pool[d], hashmix(pool[s]));

    uint32_t hb = INIT_B;
    uint32_t st32[8];
    for (int i = 0; i < 8; i++) {
        uint32_t dv = pool[i & 3];
        dv ^= hb; hb *= MULT_B; dv *= hb; dv ^= dv >> 16;
        st32[i] = dv;
    }
    uint64_t s64[4];
    for (int i = 0; i < 4; i++)
        s64[i] = (uint64_t)st32[2 * i] | ((uint64_t)st32[2 * i + 1] << 32);

    NpRng rng;
    u128 initstate = ((u128)s64[0] << 64) | s64[1];
    u128 initseq   = ((u128)s64[2] << 64) | s64[3];
    rng.inc   = (initseq << 1) | 1;
    rng.state = 0;
    rng.state = rng.state * NpRng::mult() + rng.inc;
    rng.state += initstate;
    rng.state = rng.state * NpRng::mult() + rng.inc;
    rng.has32 = false;
    rng.buf32 = 0;

    Plan plan;
    plan.n = 0;
    for (int l = 0; l < 2; l++) {
        int i = 0;
        while (i < 4 && plan.n < MAXOPS) {
            if (rng.nextDouble() > 0.3) {
                int g = (int)rng.lemire32(2);
                int w = (int)rng.lemire32(3);
                plan.type[plan.n] = g;
                plan.a[plan.n]    = w;
                plan.b[plan.n]    = 0;
                plan.widx[plan.n] = l * 4 + i;
                plan.n++;
                i++;
            } else {
                uint64_t hash_set[4] = { ~0ULL, ~0ULL, ~0ULL, ~0ULL };
                int64_t idx[2];
                for (int jf = 2; jf <= 3; jf++) {
                    uint64_t val = (uint64_t)rng.lemire32((uint32_t)jf);
                    uint64_t loc = val & 3;
                    while (hash_set[loc] != ~0ULL && hash_set[loc] != val)
                        loc = (loc + 1) & 3;
                    if (hash_set[loc] == ~0ULL) {
                        hash_set[loc] = val;
                        idx[jf - 2] = (int64_t)val;
                    } else {
                        loc = (uint64_t)jf & 3;
                        while (hash_set[loc] != ~0ULL) loc = (loc + 1) & 3;
                        hash_set[loc] = (uint64_t)jf;
                        idx[jf - 2] = jf;
                    }
                }
                uint32_t sh = rng.lemire32(1u);   // Lemire-32 (top bit)
                int64_t tmp = idx[1]; idx[1] = idx[sh]; idx[sh] = tmp;

                plan.type[plan.n] = 3;
                plan.a[plan.n]    = (int)idx[0];
                plan.b[plan.n]    = (int)idx[1];
                plan.widx[plan.n] = 0;
                plan.n++;
            }
        }
    }
    return plan;
}

// ---------------------------------------------------------------------------
extern "C" void kernel_launch(void* const* d_in, const int* in_sizes, int n_in,
                              void* d_out, int out_size) {
    const float* x  = (const float*)d_in[0];
    const float* w1 = (const float*)d_in[1];
    const float* w2 = (const float*)d_in[2];
    float* out = (float*)d_out;

    Plan plan = make_plan_host();

    build_W_kernel<<<2, 256>>>(w1, w2, plan);
    qconv_main_kernel<<<1280, 128>>>(x, out);
}